// round 17
// baseline (speedup 1.0000x reference)
#include <cuda_runtime.h>
#include <cuda_bf16.h>
#include <cstdint>

#define BATCH 2048
#define NIN   2048
#define NG    8192
#define NCOL  16384  // NG*2

// ---------------------------------------------------------------------------
// Scratch (static device globals -- allocation-free rule)
__device__ __align__(1024) __nv_bfloat16 g_Pt[(size_t)NCOL * NIN];  // exp(c)^T, 67 MB
__device__ __align__(1024) __nv_bfloat16 g_xb[(size_t)BATCH * NIN]; // x bf16, 8 MB
__device__ float  g_spart[8 * NCOL];
__device__ float4 g_coef4[NG];     // (alpha, beta, gamma, delta) per gate

// Task queue + readiness flags (reset every call by k_reset)
__device__ int g_task;        // next task id
__device__ int g_cf[64];      // coef task done (1 per task; gates [ct*128,+128))
__device__ int g_xf[16];      // xcvt rows done per bm group (target 128)
__device__ int g_ef[256];     // exp tiles done per bx (target 8)

#define N_COEF 64
#define N_XCVT 2048
#define N_EXP  2048
#define NPREP  (N_COEF + N_XCVT + N_EXP)   // 4160

__device__ __forceinline__ uint32_t smem_to_u32(const void* p) {
    uint32_t a;
    asm("{ .reg .u64 t; cvta.to.shared.u64 t, %1; cvt.u32.u64 %0, t; }" : "=r"(a) : "l"(p));
    return a;
}
__device__ __forceinline__ int vld(const int* p) { return *(volatile const int*)p; }

// ---------------------------------------------------------------------------
__global__ void k_reset() {
    int i = threadIdx.x;
    if (i == 0) g_task = 0;
    if (i < 64)  g_cf[i] = 0;
    if (i < 16)  g_xf[i] = 0;
    if (i < 256) g_ef[i] = 0;
}

// ---------------------------------------------------------------------------
// Main kernel: task-stealing prep (coef / xcvt / exp-transpose) fused with the
// R15 GEMM. CTA 128x128, BK=32, 4-stage cp.async, 128 threads, 2 CTAs/SM.
#define BM 128
#define BN 128
#define BK 32
#define STAGES 4
#define LDSB 80
#define A_BYTES (BM * LDSB)           // 10240
#define B_BYTES (BN * LDSB)           // 10240
#define STG (A_BYTES + B_BYTES)       // 20480
#define DYN_SMEM (STAGES * STG)       // 81920 (x2 CTAs = 160KB/SM)
#define NKT (NIN / BK)                // 64

#define CP_ASYNC(dst, src) \
    asm volatile("cp.async.cg.shared.global [%0], [%1], 16;" :: "r"(dst), "l"(src) : "memory")
#define CP_COMMIT() asm volatile("cp.async.commit_group;" ::: "memory")
#define CP_WAIT2()  asm volatile("cp.async.wait_group 2;" ::: "memory")

__device__ __forceinline__ void ldsm4(uint32_t& r0, uint32_t& r1, uint32_t& r2, uint32_t& r3, uint32_t a) {
    asm volatile("ldmatrix.sync.aligned.m8n8.x4.shared.b16 {%0,%1,%2,%3}, [%4];"
                 : "=r"(r0), "=r"(r1), "=r"(r2), "=r"(r3) : "r"(a));
}
__device__ __forceinline__ void mma16816(float* d, const uint32_t* a, uint32_t b0, uint32_t b1) {
    asm volatile("mma.sync.aligned.m16n8k16.row.col.f32.bf16.bf16.f32 "
                 "{%0,%1,%2,%3}, {%4,%5,%6,%7}, {%8,%9}, {%0,%1,%2,%3};"
                 : "+f"(d[0]), "+f"(d[1]), "+f"(d[2]), "+f"(d[3])
                 : "r"(a[0]), "r"(a[1]), "r"(a[2]), "r"(a[3]), "r"(b0), "r"(b1));
}

__global__ __launch_bounds__(128, 2) void k_main(const float* __restrict__ c,
                                                 const float* __restrict__ x,
                                                 const float* __restrict__ w,
                                                 float* __restrict__ out) {
    extern __shared__ __align__(128) unsigned char dynsm[];
    __shared__ int s_task;

    const int tid = threadIdx.x;
    const int bn = blockIdx.x, bm = blockIdx.y;

    // ===================== Phase 1: steal prep tasks until ready ==========
    for (;;) {
        if (tid == 0) {
            bool ready = (vld(&g_xf[bm]) == 128) &&
                         (vld(&g_ef[2 * bn]) == 8) && (vld(&g_ef[2 * bn + 1]) == 8);
            int tk;
            if (ready) tk = -1;
            else { tk = atomicAdd(&g_task, 1); if (tk >= NPREP) tk = -2; }
            s_task = tk;
        }
        __syncthreads();
        const int tk = s_task;
        __syncthreads();
        if (tk == -1) break;
        if (tk == -2) {            // queue empty: wait for our flags
            if (tid == 0) {
                while (!((vld(&g_xf[bm]) == 128) &&
                         (vld(&g_ef[2 * bn]) == 8) && (vld(&g_ef[2 * bn + 1]) == 8)))
                    __nanosleep(200);
            }
            __syncthreads();
            break;
        }
        if (tk < N_COEF) {
            // ---- coef task: gates [tk*128, +128), one per thread
            int g = tk * 128 + tid;
            float v[16];
            float m = -1e30f;
#pragma unroll
            for (int k = 0; k < 16; ++k) { v[k] = w[k * NG + g]; m = fmaxf(m, v[k]); }
            float sum = 0.f;
#pragma unroll
            for (int k = 0; k < 16; ++k) { v[k] = __expf(v[k] - m); sum += v[k]; }
            float inv = 1.f / sum;
#pragma unroll
            for (int k = 0; k < 16; ++k) v[k] *= inv;
            float al = v[8]+v[9]+v[10]+v[11]+v[12]+v[13]+v[14]+v[15];
            float be = v[2]+v[3]+v[6]+v[7] - v[8]-v[9]-v[12]-v[13];
            float ga = v[4]+v[5]+v[6]+v[7] - v[8]-v[9]-v[10]-v[11];
            float de = v[1]-v[2]-v[4]-2.f*v[6]-v[7]+v[8]+2.f*v[9]+v[11]+v[13]-v[14];
            g_coef4[g] = make_float4(al, be, ga, de);
            __syncthreads();
            if (tid == 0) { __threadfence(); atomicAdd(&g_cf[tk], 1); }
        } else if (tk < N_COEF + N_XCVT) {
            // ---- xcvt task: one xb row (2048 elements)
            const int r = tk - N_COEF;
            const size_t base = (size_t)r * NIN;
#pragma unroll
            for (int q = 0; q < 4; ++q) {
                size_t i = base + q * 512 + tid * 4;
                float4 rd = *(const float4*)(x + i);
                *(__nv_bfloat162*)(g_xb + i)     = __floats2bfloat162_rn(rd.x, rd.y);
                *(__nv_bfloat162*)(g_xb + i + 2) = __floats2bfloat162_rn(rd.z, rd.w);
            }
            __syncthreads();
            if (tid == 0) { __threadfence(); atomicAdd(&g_xf[r >> 7], 1); }
        } else {
            // ---- exp task: 64j x 256i tile, [j][i] staged transpose + col sums
            const int e = tk - N_COEF - N_XCVT;
            const int bx = e >> 3, by = e & 7;
            const int j0 = bx * 64, i0 = by * 256;
            __nv_bfloat16 (*sm)[258] = (__nv_bfloat16 (*)[258])dynsm;
            float (*ssum)[64] = (float (*)[64])(dynsm + 64 * 258 * 2);
            const int tj = tid & 31, ti = tid >> 5;
            float s0 = 0.f, s1 = 0.f;
#pragma unroll 8
            for (int it = 0; it < 64; ++it) {
                int il = ti + 4 * it;
                float2 rd = *(const float2*)(c + (size_t)(i0 + il) * NCOL + j0 + 2 * tj);
                float e0 = __expf(rd.x), e1 = __expf(rd.y);
                sm[2 * tj][il]     = __float2bfloat16(e0);
                sm[2 * tj + 1][il] = __float2bfloat16(e1);
                s0 += e0; s1 += e1;
            }
            ssum[ti][2 * tj] = s0;
            ssum[ti][2 * tj + 1] = s1;
            __syncthreads();
            if (tid < 64) {
                float t = ssum[0][tid] + ssum[1][tid] + ssum[2][tid] + ssum[3][tid];
                g_spart[by * NCOL + j0 + tid] = t;
            }
#pragma unroll 8
            for (int it = 0; it < 64; ++it) {
                __nv_bfloat162 pk;
                pk.x = sm[it][2 * tid];
                pk.y = sm[it][2 * tid + 1];
                *(__nv_bfloat162*)(g_Pt + (size_t)(j0 + it) * NIN + i0 + 2 * tid) = pk;
            }
            __syncthreads();
            if (tid == 0) { __threadfence(); atomicAdd(&g_ef[bx], 1); }
        }
        __syncthreads();   // smem (s_task / staging) reuse safety
    }
    __threadfence();       // acquire: flags observed -> producer writes visible
    __syncthreads();

    // ===================== Phase 2: GEMM (R15 structure, unchanged) =======
    const uint32_t sbase = smem_to_u32(dynsm);
    const int wid = tid >> 5, lane = tid & 31;
    const int wm = wid >> 1, wn = wid & 1;      // 2x2 warp grid, warp tile 64x64

    const int ar = tid >> 2, ac = tid & 3;       // ar 0..31, ac 0..3
    const __nv_bfloat16* gA = g_xb + (size_t)(bm * BM + ar) * NIN + ac * 8;
    const __nv_bfloat16* gB = g_Pt + (size_t)(bn * BN + ar) * NIN + ac * 8;

    float acc[4][8][4];
#pragma unroll
    for (int mi = 0; mi < 4; ++mi)
#pragma unroll
        for (int ni = 0; ni < 8; ++ni)
#pragma unroll
            for (int q = 0; q < 4; ++q) acc[mi][ni][q] = 0.f;

    auto load_stage = [&](int s, int t) {
        const uint32_t sa = sbase + s * STG;
        const uint32_t sb = sa + A_BYTES;
        const int koff = t * BK;
#pragma unroll
        for (int i = 0; i < 4; ++i) {
            CP_ASYNC(sa + (ar + i * 32) * LDSB + ac * 16, gA + (size_t)(i * 32) * NIN + koff);
            CP_ASYNC(sb + (ar + i * 32) * LDSB + ac * 16, gB + (size_t)(i * 32) * NIN + koff);
        }
    };

    const uint32_t aLaneOff = (uint32_t)((lane & 15) * LDSB + (lane >> 4) * 16) + (uint32_t)(wm * 64) * LDSB;
    const uint32_t bLaneOff = (uint32_t)(((lane & 7) + ((lane >> 4) << 3)) * LDSB + ((lane >> 3) & 1) * 16)
                            + (uint32_t)(wn * 64) * LDSB + A_BYTES;

    uint32_t af[2][4][4], bf[2][4][4];

    auto load_frags = [&](int buf, int t, uint32_t ko) {
        const uint32_t sg = sbase + (t % STAGES) * STG + ko;
#pragma unroll
        for (int mi = 0; mi < 4; ++mi)
            ldsm4(af[buf][mi][0], af[buf][mi][1], af[buf][mi][2], af[buf][mi][3],
                  sg + (uint32_t)(mi * 16) * LDSB + aLaneOff);
#pragma unroll
        for (int nj = 0; nj < 4; ++nj)
            ldsm4(bf[buf][nj][0], bf[buf][nj][1], bf[buf][nj][2], bf[buf][nj][3],
                  sg + (uint32_t)(nj * 16) * LDSB + bLaneOff);
    };
    auto mma_all = [&](int buf) {
#pragma unroll
        for (int mi = 0; mi < 4; ++mi)
#pragma unroll
            for (int nj = 0; nj < 4; ++nj) {
                mma16816(acc[mi][2 * nj],     af[buf][mi], bf[buf][nj][0], bf[buf][nj][1]);
                mma16816(acc[mi][2 * nj + 1], af[buf][mi], bf[buf][nj][2], bf[buf][nj][3]);
            }
    };

#pragma unroll
    for (int s = 0; s < STAGES - 1; ++s) { load_stage(s, s); CP_COMMIT(); }
    CP_WAIT2();
    __syncthreads();
    load_frags(0, 0, 0);

    for (int t = 0; t < NKT; ++t) {
        load_frags(1, t, 32);

        if (t + STAGES - 1 < NKT) load_stage((t + STAGES - 1) % STAGES, t + STAGES - 1);
        CP_COMMIT();

        mma_all(0);

        CP_WAIT2();
        __syncthreads();

        const int tn = (t + 1 < NKT) ? t + 1 : t;
        load_frags(0, tn, 0);
        mma_all(1);
    }

    // ------------------------------------------------------------------
    // Epilogue: gate coef readiness, per-CTA reciprocal table, fused gates.
    if (tid == 0) {
        while (vld(&g_cf[bn >> 1]) == 0) __nanosleep(200);
    }
    __syncthreads();
    __threadfence();

    float* srec = (float*)dynsm;
    {
        int j = bn * BN + tid;
        float s = 0.f;
#pragma unroll
        for (int k = 0; k < 8; ++k) s += g_spart[k * NCOL + j];
        srec[tid] = 1.f / s;
    }
    __syncthreads();

    const int row0 = bm * BM + wm * 64 + (lane >> 2);
    const int lg0 = wn * 32 + (lane & 3);
    const int gbase = bn * (BN / 2) + lg0;
#pragma unroll
    for (int ni = 0; ni < 8; ++ni) {
        const int g = gbase + ni * 4;
        const float2 rsv = *(const float2*)(srec + 2 * (lg0 + ni * 4));
        const float4 cf = g_coef4[g];
#pragma unroll
        for (int mi = 0; mi < 4; ++mi) {
            const float* d = acc[mi][ni];
            float Av = d[0] * rsv.x, Bv = d[1] * rsv.y;
            out[(size_t)(row0 + mi * 16) * NG + g] =
                cf.x + cf.y * Av + cf.z * Bv + cf.w * (Av * Bv);
            Av = d[2] * rsv.x; Bv = d[3] * rsv.y;
            out[(size_t)(row0 + mi * 16 + 8) * NG + g] =
                cf.x + cf.y * Av + cf.z * Bv + cf.w * (Av * Bv);
        }
    }
}

// ---------------------------------------------------------------------------
extern "C" void kernel_launch(void* const* d_in, const int* in_sizes, int n_in,
                              void* d_out, int out_size) {
    const float* x = (const float*)d_in[0];  // (2048, 2048)
    const float* w = (const float*)d_in[1];  // (16, 8192)
    const float* c = (const float*)d_in[2];  // (2048, 8192, 2)
    float* out = (float*)d_out;              // (2048, 8192)

    cudaFuncSetAttribute(k_main, cudaFuncAttributeMaxDynamicSharedMemorySize, DYN_SMEM);

    k_reset<<<1, 512>>>();
    k_main<<<dim3(NCOL / BN, BATCH / BM), 128, DYN_SMEM>>>(c, x, w, out);
}